// round 9
// baseline (speedup 1.0000x reference)
#include <cuda_runtime.h>
#include <cstdint>

#define Bz 128
#define Sz 512
#define Hz 256
#define Vz 256
#define NCTA 128

typedef unsigned long long ull;

// Rotating h exchange buffer: slot 0 = h0 = zeros (never written).
// h_t lives in slot (t==0 ? 0 : 1+((t-1)&1)).  ~384 KB -> L2-resident.
__device__ float g_h[3][Bz][Hz];
// one barrier counter per b-tile, padded to its own 128-B L2 line
__device__ unsigned g_bar[16 * 32];        // use index [bt * 32]
__device__ unsigned g_done = 0;            // end-of-kernel reset rendezvous

__device__ __forceinline__ void fma2(ull& acc, ull a, ull b) {
    asm("fma.rn.f32x2 %0, %1, %2, %3;" : "=l"(acc) : "l"(a), "l"(b), "l"(acc));
}
__device__ __forceinline__ float f2sum(ull v) {
    return __uint_as_float((unsigned)v) + __uint_as_float((unsigned)(v >> 32));
}
__device__ __forceinline__ float sigmf(float v) { return 1.0f / (1.0f + __expf(-v)); }
__device__ __forceinline__ int hidx(int t) { return t == 0 ? 0 : 1 + ((t - 1) & 1); }

// ---- dynamic smem layout (offsets in floats) ----
#define OFF_WRZ 0        // float4[128 kp][32 j] = (r_k,r_k1,z_k,z_k1)   64 KB
#define OFF_WN  16384    // float2[128 kp][32 j] = (n_k,n_k1)            32 KB
#define OFF_H   24576    // float [8 b][256 k]                            8 KB
#define OFF_RED 26624    // float4[8 kc][8 b][32 j]                      32 KB
#define OFF_WIH 34816    // float4[16 e][32 j]                            8 KB
#define OFF_EMB 36864    // float [256 v][17]                            17 KB
#define OFF_X   41216    // int   [8 b][512 s]                           16 KB
#define OFF_WO  45312    // float2[128 kp][32 v] W_out k-pairs           32 KB
#define SM1_FLOATS 53504 // 214016 bytes

__device__ __forceinline__ float3 compute_gi(const float* sm, int b, int j2,
                                             int t, float3 bih) {
    const int* xs = (const int*)(sm + OFF_X);
    int xv = xs[b * Sz + t];
    float3 acc = bih;
    const float* emb = sm + OFF_EMB;
    const float4* wih = (const float4*)(sm + OFF_WIH);
#pragma unroll
    for (int e = 0; e < 16; ++e) {
        float ev = emb[xv * 17 + e];
        float4 wv = wih[e * 32 + j2];
        acc.x += ev * wv.x; acc.y += ev * wv.y; acc.z += ev * wv.z;
    }
    return acc;
}

// out[:, trow] tile for this CTA: thread = (warp b, lane v), v-range = j-range.
// h via LDS.64 broadcast, W via conflict-free k-pair float2s; 4-way ILP chains.
__device__ __forceinline__ void out_gemm(const float* hs, const float* wo2f,
                                         int bW, int vL, float bov,
                                         float* __restrict__ out,
                                         int b0, int j0, int trow) {
    ull a0 = 0ull, a1 = 0ull, a2 = 0ull, a3 = 0ull;
    const float* hrow = hs + bW * 256;
    const float* wp = wo2f + 2 * vL;
#pragma unroll 8
    for (int kp = 0; kp < 128; kp += 4) {
        ull h0 = *(const ull*)&hrow[2 * kp];
        ull h1 = *(const ull*)&hrow[2 * kp + 2];
        ull h2 = *(const ull*)&hrow[2 * kp + 4];
        ull h3 = *(const ull*)&hrow[2 * kp + 6];
        fma2(a0, h0, *(const ull*)&wp[(kp + 0) * 64]);
        fma2(a1, h1, *(const ull*)&wp[(kp + 1) * 64]);
        fma2(a2, h2, *(const ull*)&wp[(kp + 2) * 64]);
        fma2(a3, h3, *(const ull*)&wp[(kp + 3) * 64]);
    }
    float r = ((f2sum(a0) + f2sum(a1)) + (f2sum(a2) + f2sum(a3))) + bov;
    out[(size_t)(b0 + bW) * (Sz * Vz) + (size_t)trow * Vz + j0 + vL] = r;
}

// ---------------------------------------------------------------------------
// Fused GRU: 128 persistent CTAs = 16 b-tiles(8) x 8 j-tiles(32).
// Per step: stage h -> FFMA2 kloop -> reduce -> finalize h -> barrier; the
// output projection out[:, t-1] = h_t @ W_out runs INSIDE the barrier wait
// (hs still holds h_t there). Post-loop emits out[:, Sz-1].
// ---------------------------------------------------------------------------
__global__ void __launch_bounds__(256, 1)
gru_fused(const int* __restrict__ x,
          const float* __restrict__ embed,
          const float* __restrict__ W_ih, const float* __restrict__ b_ih,
          const float* __restrict__ W_hh, const float* __restrict__ b_hh,
          const float* __restrict__ W_out, const float* __restrict__ b_out,
          float* __restrict__ out)
{
    extern __shared__ float sm[];
    const int tid = threadIdx.x;
    const int jt = blockIdx.x & 7, bt = blockIdx.x >> 3;
    const int j0 = jt * 32, b0 = bt * 8;

    // ---- one-time fills ----
    float4* wrz4 = (float4*)(sm + OFF_WRZ);
    float2* wn2  = (float2*)(sm + OFF_WN);
    for (int i = tid; i < 128 * 32; i += 256) {
        int kp = i >> 5, j2 = i & 31, jg = j0 + j2;
        const float* wr0 = W_hh + (2 * kp) * 768 + jg;
        const float* wr1 = W_hh + (2 * kp + 1) * 768 + jg;
        wrz4[i] = make_float4(wr0[0], wr1[0], wr0[256], wr1[256]);
        wn2[i]  = make_float2(wr0[512], wr1[512]);
    }
    for (int i = tid; i < Vz * 16; i += 256) {
        int v = i >> 4, e = i & 15;
        sm[OFF_EMB + v * 17 + e] = embed[i];
    }
    {
        float4* wih4 = (float4*)(sm + OFF_WIH);
        for (int i = tid; i < 16 * 32; i += 256) {
            int e = i >> 5, j2 = i & 31, jg = j0 + j2;
            wih4[i] = make_float4(W_ih[e * 768 + jg], W_ih[e * 768 + 256 + jg],
                                  W_ih[e * 768 + 512 + jg], 0.f);
        }
    }
    {
        int4* xs4 = (int4*)(sm + OFF_X);
        const int4* xg = (const int4*)x;
        for (int i = tid; i < 1024; i += 256) {
            int bb = i >> 7, s4 = i & 127;
            xs4[i] = xg[(b0 + bb) * 128 + s4];
        }
    }
    // W_out k-pair tile for this CTA's v-range (v = j0 + 0..31)
    for (int i = tid; i < 128 * 32; i += 256) {
        int kp = i >> 5, v = i & 31;
        sm[OFF_WO + kp * 64 + 2 * v]     = W_out[(2 * kp) * 256 + j0 + v];
        sm[OFF_WO + kp * 64 + 2 * v + 1] = W_out[(2 * kp + 1) * 256 + j0 + v];
    }

    // per-thread finalize identity (b, j2) + register-resident biases
    const int bF = tid >> 5, j2F = tid & 31, jF = j0 + j2F;
    float3 bih = make_float3(b_ih[jF], b_ih[256 + jF], b_ih[512 + jF]);
    float3 bhh = make_float3(b_hh[jF], b_hh[256 + jF], b_hh[512 + jF]);
    const float bov = b_out[jF];       // out bias for (lane v = j2F)

    __syncthreads();
    float3 gi = compute_gi(sm, bF, j2F, 0, bih);

    const int w  = tid >> 5;
    const int jl = tid & 31;
    float*  hs   = sm + OFF_H;
    float4* red4 = (float4*)(sm + OFF_RED);
    const float* wo2f = sm + OFF_WO;
    unsigned* mybar = &g_bar[bt * 32];

    for (int t = 0; t < Sz; ++t) {
        // ---- stage h_t tile: 8 rows x 256, coalesced ----
        {
            const float* hsrc = &g_h[hidx(t)][b0 + w][0];
            float4 A = *(const float4*)&hsrc[jl * 4];
            float4 B = *(const float4*)&hsrc[128 + jl * 4];
            *(float4*)&hs[w * 256 + jl * 4]       = A;
            *(float4*)&hs[w * 256 + 128 + jl * 4] = B;
        }
        __syncthreads();   // h_s ready

        // ---- k-chunk loop: FFMA2 over k-pairs ----
        ull ar[8], az[8], an[8];
#pragma unroll
        for (int b = 0; b < 8; ++b) { ar[b] = 0ull; az[b] = 0ull; an[b] = 0ull; }
        const int kp0 = w * 16;
#pragma unroll
        for (int q = 0; q < 8; ++q) {            // k-quads (4 k = 2 kpairs)
            const int kb = kp0 * 2 + q * 4;
            ulonglong2 h01[8];
#pragma unroll
            for (int b = 0; b < 8; ++b)
                h01[b] = *(const ulonglong2*)&hs[b * 256 + kb];
#pragma unroll
            for (int p = 0; p < 2; ++p) {
                const int kp = kp0 + q * 2 + p;
                ulonglong2 wrz = *(const ulonglong2*)&wrz4[kp * 32 + jl];
                ull        wn  = *(const ull*)&wn2[kp * 32 + jl];
#pragma unroll
                for (int b = 0; b < 8; ++b) {
                    ull h = p ? h01[b].y : h01[b].x;
                    fma2(ar[b], h, wrz.x);
                    fma2(az[b], h, wrz.y);
                    fma2(an[b], h, wn);
                }
            }
        }
#pragma unroll
        for (int b = 0; b < 8; ++b)
            red4[(w * 8 + b) * 32 + jl] =
                make_float4(f2sum(ar[b]), f2sum(az[b]), f2sum(an[b]), 0.f);
        __syncthreads();

        // ---- finalize gates: one (b, j) pair per thread ----
        {
            float sr = 0.f, szz = 0.f, sn = 0.f;
#pragma unroll
            for (int kc = 0; kc < 8; ++kc) {
                float4 p = red4[(kc * 8 + bF) * 32 + j2F];
                sr += p.x; szz += p.y; sn += p.z;
            }
            float hprev = hs[bF * 256 + jF];
            float r = sigmf(gi.x + sr + bhh.x);
            float z = sigmf(gi.y + szz + bhh.y);
            float n = tanhf(gi.z + r * (sn + bhh.z));
            g_h[1 + (t & 1)][b0 + bF][jF] = (1.0f - z) * n + z * hprev;
        }

        // ---- per-b-tile barrier; out[:, t-1] fills the wait ----
        __threadfence();              // release h writes at gpu scope
        __syncthreads();
        if (tid == 0) atomicAdd(mybar, 1u);

        if (t + 1 < Sz) gi = compute_gi(sm, bF, j2F, t + 1, bih);
        if (t > 0)                    // hs still holds h_t here
            out_gemm(hs, wo2f, w, jl, bov, out, b0, j0, t - 1);

        if (tid == 0) {
            unsigned target = (unsigned)(t + 1) * 8u;
            while (*(volatile unsigned*)mybar < target) { }
            __threadfence();          // acquire peer CTAs' h writes
        }
        __syncthreads();
    }

    // ---- final row: stage h_512 and emit out[:, Sz-1] ----
    {
        const float* hsrc = &g_h[hidx(Sz)][b0 + w][0];
        float4 A = *(const float4*)&hsrc[jl * 4];
        float4 B = *(const float4*)&hsrc[128 + jl * 4];
        *(float4*)&hs[w * 256 + jl * 4]       = A;
        *(float4*)&hs[w * 256 + 128 + jl * 4] = B;
    }
    __syncthreads();
    out_gemm(hs, wo2f, w, jl, bov, out, b0, j0, Sz - 1);

    // reset counters for graph replay: last CTA to finish resets all shards
    // (every other CTA has passed its final poll before incrementing g_done).
    __threadfence();
    if (tid == 0) {
        unsigned d = atomicAdd(&g_done, 1u);
        if (d == NCTA - 1u) {
            for (int i = 0; i < 16; ++i) g_bar[i * 32] = 0u;
            g_done = 0u;
            __threadfence();
        }
    }
}

extern "C" void kernel_launch(void* const* d_in, const int* in_sizes, int n_in,
                              void* d_out, int out_size)
{
    const int*   x     = (const int*)  d_in[0];
    const float* embed = (const float*)d_in[1];
    const float* W_ih  = (const float*)d_in[2];
    const float* b_ih  = (const float*)d_in[3];
    const float* W_hh  = (const float*)d_in[4];
    const float* b_hh  = (const float*)d_in[5];
    const float* W_out = (const float*)d_in[6];
    const float* b_out = (const float*)d_in[7];
    float* out = (float*)d_out;

    cudaFuncSetAttribute(gru_fused, cudaFuncAttributeMaxDynamicSharedMemorySize,
                         SM1_FLOATS * 4);
    gru_fused<<<NCTA, 256, SM1_FLOATS * 4>>>(x, embed, W_ih, b_ih, W_hh, b_hh,
                                             W_out, b_out, out);
}

// round 10
// speedup vs baseline: 1.4935x; 1.4935x over previous
#include <cuda_runtime.h>
#include <cstdint>

#define Bz 128
#define Sz 512
#define Hz 256
#define Vz 256
#define NCTA 128

typedef unsigned long long ull;

// h sequence, slab 0 = h0 = zeros (never written). Layout [t][b][j].
__device__ float g_hseq[Sz + 1][Bz][Hz];   // ~67 MB, zero-init at module load
// one barrier counter per b-tile, padded to its own 128-B L2 line
__device__ unsigned g_bar[16 * 32];        // use index [bt * 32]
__device__ unsigned g_done = 0;            // end-of-kernel reset rendezvous

__device__ __forceinline__ void fma2(ull& acc, ull a, ull b) {
    asm("fma.rn.f32x2 %0, %1, %2, %3;" : "=l"(acc) : "l"(a), "l"(b), "l"(acc));
}
__device__ __forceinline__ float f2sum(ull v) {
    return __uint_as_float((unsigned)v) + __uint_as_float((unsigned)(v >> 32));
}
__device__ __forceinline__ float sigmf(float v) { return 1.0f / (1.0f + __expf(-v)); }

// cooperative-grid-sync style primitives: no worker-thread gpu membars.
__device__ __forceinline__ void red_release_gpu(unsigned* p) {
    asm volatile("red.release.gpu.add.u32 [%0], 1;" :: "l"(p) : "memory");
}
__device__ __forceinline__ unsigned ld_acquire_gpu(unsigned* p) {
    unsigned v;
    asm volatile("ld.acquire.gpu.u32 %0, [%1];" : "=r"(v) : "l"(p) : "memory");
    return v;
}

// ---- phase-1 dynamic smem layout (offsets in floats) ----
#define OFF_WRZ 0        // float4[128 kp][32 j] = (r_k,r_k1,z_k,z_k1)   64 KB
#define OFF_WN  16384    // float2[128 kp][32 j] = (n_k,n_k1)            32 KB
#define OFF_H   24576    // float [8 b][256 k]                            8 KB
#define OFF_RED 26624    // float4[8 kc][8 b][32 j]                      32 KB
#define OFF_WIH 34816    // float4[16 e][32 j]                            8 KB
#define OFF_EMB 36864    // float [256 v][17]                            17 KB
#define OFF_X   41216    // int   [8 b][512 s]                           16 KB
#define SM1_FLOATS 45312 // 181248 bytes

__device__ __forceinline__ float3 compute_gi(const float* sm, int b, int j2,
                                             int t, float3 bih) {
    const int* xs = (const int*)(sm + OFF_X);
    int xv = xs[b * Sz + t];
    float3 acc = bih;
    const float* emb = sm + OFF_EMB;
    const float4* wih = (const float4*)(sm + OFF_WIH);
#pragma unroll
    for (int e = 0; e < 16; ++e) {
        float ev = emb[xv * 17 + e];
        float4 wv = wih[e * 32 + j2];
        acc.x += ev * wv.x; acc.y += ev * wv.y; acc.z += ev * wv.z;
    }
    return acc;
}

// ---------------------------------------------------------------------------
// Phase 1: persistent GRU recurrence. 128 CTAs = 16 b-tiles(8) x 8 j-tiles(32).
// 8 warps = 8 k-chunks (16 k-pairs); lane = j; FFMA2 over k-pairs.
// Sync: per-b-tile counter (8 arrivals, private L2 line) with
// red.release.gpu arrival + ld.acquire.gpu poll -- the cooperative grid.sync
// pattern; no gpu-scope MEMBAR from worker threads.
// ---------------------------------------------------------------------------
__global__ void __launch_bounds__(256, 1)
gru_phase1(const int* __restrict__ x,
           const float* __restrict__ embed,
           const float* __restrict__ W_ih, const float* __restrict__ b_ih,
           const float* __restrict__ W_hh, const float* __restrict__ b_hh)
{
    extern __shared__ float sm[];
    const int tid = threadIdx.x;
    const int jt = blockIdx.x & 7, bt = blockIdx.x >> 3;
    const int j0 = jt * 32, b0 = bt * 8;

    // ---- one-time fills ----
    float4* wrz4 = (float4*)(sm + OFF_WRZ);
    float2* wn2  = (float2*)(sm + OFF_WN);
    for (int i = tid; i < 128 * 32; i += 256) {
        int kp = i >> 5, j2 = i & 31, jg = j0 + j2;
        const float* wr0 = W_hh + (2 * kp) * 768 + jg;
        const float* wr1 = W_hh + (2 * kp + 1) * 768 + jg;
        wrz4[i] = make_float4(wr0[0], wr1[0], wr0[256], wr1[256]);
        wn2[i]  = make_float2(wr0[512], wr1[512]);
    }
    for (int i = tid; i < Vz * 16; i += 256) {
        int v = i >> 4, e = i & 15;
        sm[OFF_EMB + v * 17 + e] = embed[i];
    }
    {
        float4* wih4 = (float4*)(sm + OFF_WIH);
        for (int i = tid; i < 16 * 32; i += 256) {
            int e = i >> 5, j2 = i & 31, jg = j0 + j2;
            wih4[i] = make_float4(W_ih[e * 768 + jg], W_ih[e * 768 + 256 + jg],
                                  W_ih[e * 768 + 512 + jg], 0.f);
        }
    }
    {
        int4* xs4 = (int4*)(sm + OFF_X);
        const int4* xg = (const int4*)x;
        for (int i = tid; i < 1024; i += 256) {
            int bb = i >> 7, s4 = i & 127;
            xs4[i] = xg[(b0 + bb) * 128 + s4];
        }
    }

    // per-thread finalize identity (b, j2) + register-resident biases
    const int bF = tid >> 5, j2F = tid & 31, jF = j0 + j2F;
    float3 bih = make_float3(b_ih[jF], b_ih[256 + jF], b_ih[512 + jF]);
    float3 bhh = make_float3(b_hh[jF], b_hh[256 + jF], b_hh[512 + jF]);

    __syncthreads();
    float3 gi = compute_gi(sm, bF, j2F, 0, bih);

    const int w  = tid >> 5;
    const int jl = tid & 31;
    float*  hs   = sm + OFF_H;
    float4* red4 = (float4*)(sm + OFF_RED);
    unsigned* mybar = &g_bar[bt * 32];

    for (int t = 0; t < Sz; ++t) {
        // ---- stage h tile: 8 rows x 256, coalesced ----
        {
            const float* hsrc = &g_hseq[t][b0 + w][0];
            float4 A = *(const float4*)&hsrc[jl * 4];
            float4 B = *(const float4*)&hsrc[128 + jl * 4];
            *(float4*)&hs[w * 256 + jl * 4]       = A;
            *(float4*)&hs[w * 256 + 128 + jl * 4] = B;
        }
        __syncthreads();   // h_s ready

        // ---- k-chunk loop: FFMA2 over k-pairs ----
        ull ar[8], az[8], an[8];
#pragma unroll
        for (int b = 0; b < 8; ++b) { ar[b] = 0ull; az[b] = 0ull; an[b] = 0ull; }
        const int kp0 = w * 16;
#pragma unroll
        for (int q = 0; q < 8; ++q) {            // k-quads (4 k = 2 kpairs)
            const int kb = kp0 * 2 + q * 4;
            ulonglong2 h01[8];
#pragma unroll
            for (int b = 0; b < 8; ++b)
                h01[b] = *(const ulonglong2*)&hs[b * 256 + kb];
#pragma unroll
            for (int p = 0; p < 2; ++p) {
                const int kp = kp0 + q * 2 + p;
                ulonglong2 wrz = *(const ulonglong2*)&wrz4[kp * 32 + jl];
                ull        wn  = *(const ull*)&wn2[kp * 32 + jl];
#pragma unroll
                for (int b = 0; b < 8; ++b) {
                    ull h = p ? h01[b].y : h01[b].x;
                    fma2(ar[b], h, wrz.x);
                    fma2(az[b], h, wrz.y);
                    fma2(an[b], h, wn);
                }
            }
        }
#pragma unroll
        for (int b = 0; b < 8; ++b)
            red4[(w * 8 + b) * 32 + jl] =
                make_float4(f2sum(ar[b]), f2sum(az[b]), f2sum(an[b]), 0.f);
        __syncthreads();

        // ---- finalize gates: one (b, j) pair per thread ----
        {
            float sr = 0.f, szz = 0.f, sn = 0.f;
#pragma unroll
            for (int kc = 0; kc < 8; ++kc) {
                float4 p = red4[(kc * 8 + bF) * 32 + j2F];
                sr += p.x; szz += p.y; sn += p.z;
            }
            float hprev = hs[bF * 256 + jF];
            float r = sigmf(gi.x + sr + bhh.x);
            float z = sigmf(gi.y + szz + bhh.y);
            float n = tanhf(gi.z + r * (sn + bhh.z));
            g_hseq[t + 1][b0 + bF][jF] = (1.0f - z) * n + z * hprev;
        }

        // ---- per-b-tile barrier (grid.sync pattern, no worker membars) ----
        if (t + 1 < Sz) {
            __syncthreads();                      // all h stores happen-before
            if (tid == 0) red_release_gpu(mybar); // release arrival, no return

            gi = compute_gi(sm, bF, j2F, t + 1, bih);   // overlap with wait

            if (tid == 0) {
                unsigned target = (unsigned)(t + 1) * 8u;
                while (ld_acquire_gpu(mybar) < target) { }
            }
            __syncthreads();                      // acquire propagates CTA-wide
        }
    }

    // reset counters for graph replay: last CTA to finish resets all shards
    // (every other CTA has passed its final poll before incrementing g_done).
    __threadfence();
    if (tid == 0) {
        unsigned d = atomicAdd(&g_done, 1u);
        if (d == NCTA - 1u) {
            for (int i = 0; i < 16; ++i) g_bar[i * 32] = 0u;
            g_done = 0u;
            __threadfence();
        }
    }
}

// ---------------------------------------------------------------------------
// Phase 2: out[b,t,:] = h_t[b,:] @ W_out + b_out.
// f32x2 paired over (k, k+1): h pairs native from [b][k] rows, w pairs native
// from transposed wsT[v][k]. Thread tile 4b x 8v = 32 f32x2 accumulators.
// Grid (512 t, 2 b-halves); 2 chunks of 128 v.
// ---------------------------------------------------------------------------
#define HP 258
#define WP 258
#define SM2_FLOATS (64 * HP + 128 * WP)   // 49536 floats = 198144 B

__global__ void __launch_bounds__(256, 1)
gru_phase2(const float* __restrict__ W_out, const float* __restrict__ b_out,
           float* __restrict__ out)
{
    extern __shared__ float sm2[];
    float* hs  = sm2;              // [64 b][HP]
    float* wsT = sm2 + 64 * HP;    // [128 v][WP]

    const int tid = threadIdx.x;
    const int t  = blockIdx.x;
    const int b0 = blockIdx.y * 64;

    for (int i = tid; i < 64 * 128; i += 256) {
        int bb = i >> 7, c2 = i & 127;
        *(float2*)&hs[bb * HP + c2 * 2] =
            *(const float2*)&g_hseq[t + 1][b0 + bb][c2 * 2];
    }

    const int bi = tid & 15;     // b-tile: 4*bi .. 4*bi+3
    const int vi = tid >> 4;     // v-tile: 8*vi .. 8*vi+7 (within chunk)

    for (int ch = 0; ch < 2; ++ch) {
        if (ch) __syncthreads();
        for (int r = 0; r < 32; ++r) {
            int i = tid + 256 * r;
            int k = i >> 5, c4 = i & 31;
            float4 wv = *(const float4*)&W_out[k * 256 + ch * 128 + c4 * 4];
            wsT[(4 * c4 + 0) * WP + k] = wv.x;
            wsT[(4 * c4 + 1) * WP + k] = wv.y;
            wsT[(4 * c4 + 2) * WP + k] = wv.z;
            wsT[(4 * c4 + 3) * WP + k] = wv.w;
        }
        __syncthreads();

        ull acc[4][8];
#pragma unroll
        for (int ib = 0; ib < 4; ++ib)
#pragma unroll
            for (int iv = 0; iv < 8; ++iv) acc[ib][iv] = 0ull;

        const float* hB = &hs[(4 * bi) * HP];
        const float* wB = &wsT[(8 * vi) * WP];

#pragma unroll 4
        for (int kp = 0; kp < 128; ++kp) {
            ull h0 = *(const ull*)&hB[0 * HP + 2 * kp];
            ull h1 = *(const ull*)&hB[1 * HP + 2 * kp];
            ull h2 = *(const ull*)&hB[2 * HP + 2 * kp];
            ull h3 = *(const ull*)&hB[3 * HP + 2 * kp];
            ull wv[8];
#pragma unroll
            for (int iv = 0; iv < 8; ++iv)
                wv[iv] = *(const ull*)&wB[iv * WP + 2 * kp];
#pragma unroll
            for (int iv = 0; iv < 8; ++iv) {
                fma2(acc[0][iv], h0, wv[iv]);
                fma2(acc[1][iv], h1, wv[iv]);
                fma2(acc[2][iv], h2, wv[iv]);
                fma2(acc[3][iv], h3, wv[iv]);
            }
        }

        int vb = ch * 128 + 8 * vi;
        float4 boA = *(const float4*)&b_out[vb];
        float4 boB = *(const float4*)&b_out[vb + 4];
#pragma unroll
        for (int ib = 0; ib < 4; ++ib) {
            float4 oA, oB;
            oA.x = f2sum(acc[ib][0]) + boA.x;
            oA.y = f2sum(acc[ib][1]) + boA.y;
            oA.z = f2sum(acc[ib][2]) + boA.z;
            oA.w = f2sum(acc[ib][3]) + boA.w;
            oB.x = f2sum(acc[ib][4]) + boB.x;
            oB.y = f2sum(acc[ib][5]) + boB.y;
            oB.z = f2sum(acc[ib][6]) + boB.z;
            oB.w = f2sum(acc[ib][7]) + boB.w;
            size_t obase = (size_t)(b0 + 4 * bi + ib) * (Sz * Vz)
                         + (size_t)t * Vz + vb;
            *(float4*)&out[obase]     = oA;
            *(float4*)&out[obase + 4] = oB;
        }
    }
}

extern "C" void kernel_launch(void* const* d_in, const int* in_sizes, int n_in,
                              void* d_out, int out_size)
{
    const int*   x     = (const int*)  d_in[0];
    const float* embed = (const float*)d_in[1];
    const float* W_ih  = (const float*)d_in[2];
    const float* b_ih  = (const float*)d_in[3];
    const float* W_hh  = (const float*)d_in[4];
    const float* b_hh  = (const float*)d_in[5];
    const float* W_out = (const float*)d_in[6];
    const float* b_out = (const float*)d_in[7];
    float* out = (float*)d_out;

    cudaFuncSetAttribute(gru_phase1, cudaFuncAttributeMaxDynamicSharedMemorySize,
                         SM1_FLOATS * 4);
    cudaFuncSetAttribute(gru_phase2, cudaFuncAttributeMaxDynamicSharedMemorySize,
                         SM2_FLOATS * 4);

    gru_phase1<<<NCTA, 256, SM1_FLOATS * 4>>>(x, embed, W_ih, b_ih, W_hh, b_hh);
    gru_phase2<<<dim3(Sz, 2), 256, SM2_FLOATS * 4>>>(W_out, b_out, out);
}